// round 6
// baseline (speedup 1.0000x reference)
#include <cuda_runtime.h>
#include <math.h>

#define DEC_DIM 1024
#define ENC_DIM 1024
#define BATCH   32
#define SRCLEN  2048

// Precomputed dec_hidden[b] . w_dec + bias
__device__ float g_edec[BATCH];

// ---------------------------------------------------------------------------
// Kernel 0: e_dec[b] = dot(dec_hidden[b,:], W[0,:1024]) + b[0]
// 1 block, 1024 threads = 32 warps, warp w handles batch row w.
// ---------------------------------------------------------------------------
__global__ void edec_kernel(const float* __restrict__ dec_hidden,
                            const float* __restrict__ W,
                            const float* __restrict__ bias) {
    const int warp = threadIdx.x >> 5;
    const int lane = threadIdx.x & 31;
    const float4* dh = reinterpret_cast<const float4*>(dec_hidden + warp * DEC_DIM);
    const float4* wd = reinterpret_cast<const float4*>(W);
    float sum = 0.f;
#pragma unroll
    for (int i = 0; i < 8; i++) {
        float4 a = dh[lane + 32 * i];
        float4 w = wd[lane + 32 * i];
        sum += a.x * w.x + a.y * w.y + a.z * w.z + a.w * w.w;
    }
#pragma unroll
    for (int o = 16; o; o >>= 1) sum += __shfl_xor_sync(0xffffffffu, sum, o);
    if (lane == 0) g_edec[warp] = sum + bias[0];
}

// ---------------------------------------------------------------------------
// Kernel 1: out[b*SRCLEN + s] = tanh( enc[s,b,:] . w_enc + e_dec[b] )
// One warp per (s,b) row. r = s*32 + b matches the memory order of
// enc_outputs, so consecutive warps stream consecutive 4KB rows.
// w_enc (4KB) staged in shared once per block.
// ---------------------------------------------------------------------------
__global__ void __launch_bounds__(256)
score_kernel(const float* __restrict__ enc,   // [SRCLEN][BATCH][ENC_DIM]
             const float* __restrict__ W,     // w_enc = W + DEC_DIM
             float* __restrict__ out) {
    __shared__ float4 s_w[ENC_DIM / 4];
    const float4* we = reinterpret_cast<const float4*>(W + DEC_DIM);
    for (int i = threadIdx.x; i < ENC_DIM / 4; i += blockDim.x) s_w[i] = we[i];
    __syncthreads();

    const int warp = threadIdx.x >> 5;
    const int lane = threadIdx.x & 31;
    const int r = blockIdx.x * 8 + warp;          // r = s*32 + b, < 65536
    const float4* row = reinterpret_cast<const float4*>(enc) + (long long)r * (ENC_DIM / 4);

    float sum = 0.f;
#pragma unroll
    for (int i = 0; i < 8; i++) {
        float4 a = row[lane + 32 * i];
        float4 w = s_w[lane + 32 * i];
        sum += a.x * w.x + a.y * w.y + a.z * w.z + a.w * w.w;
    }
#pragma unroll
    for (int o = 16; o; o >>= 1) sum += __shfl_xor_sync(0xffffffffu, sum, o);

    if (lane == 0) {
        const int b = r & 31;
        const int s = r >> 5;
        out[b * SRCLEN + s] = tanhf(sum + g_edec[b]);
    }
}

// ---------------------------------------------------------------------------
// Kernel 2: in-place softmax over s (2048) for each batch row.
// 32 blocks x 256 threads; 8 values/thread held in registers.
// ---------------------------------------------------------------------------
__global__ void __launch_bounds__(256)
softmax_kernel(float* __restrict__ out) {
    float* row = out + blockIdx.x * SRCLEN;
    const int t = threadIdx.x;
    __shared__ float red[8];
    __shared__ float s_bcast;

    float v[8];
    float mx = -1e30f;
#pragma unroll
    for (int i = 0; i < 8; i++) {
        v[i] = row[t + 256 * i];
        mx = fmaxf(mx, v[i]);
    }
#pragma unroll
    for (int o = 16; o; o >>= 1) mx = fmaxf(mx, __shfl_xor_sync(0xffffffffu, mx, o));
    if ((t & 31) == 0) red[t >> 5] = mx;
    __syncthreads();
    if (t == 0) {
        float m = red[0];
#pragma unroll
        for (int i = 1; i < 8; i++) m = fmaxf(m, red[i]);
        s_bcast = m;
    }
    __syncthreads();
    const float m = s_bcast;

    float s = 0.f;
#pragma unroll
    for (int i = 0; i < 8; i++) {
        v[i] = expf(v[i] - m);
        s += v[i];
    }
#pragma unroll
    for (int o = 16; o; o >>= 1) s += __shfl_xor_sync(0xffffffffu, s, o);
    if ((t & 31) == 0) red[t >> 5] = s;
    __syncthreads();
    if (t == 0) {
        float tot = red[0];
#pragma unroll
        for (int i = 1; i < 8; i++) tot += red[i];
        s_bcast = 1.0f / tot;
    }
    __syncthreads();
    const float inv = s_bcast;

#pragma unroll
    for (int i = 0; i < 8; i++) row[t + 256 * i] = v[i] * inv;
}

// ---------------------------------------------------------------------------
extern "C" void kernel_launch(void* const* d_in, const int* in_sizes, int n_in,
                              void* d_out, int out_size) {
    const float* dec_hidden = (const float*)d_in[0];
    const float* enc        = (const float*)d_in[1];
    const float* W          = (const float*)d_in[2];
    const float* bias       = (const float*)d_in[3];
    float* out = (float*)d_out;

    edec_kernel<<<1, 1024>>>(dec_hidden, W, bias);
    score_kernel<<<(SRCLEN * BATCH) / 8, 256>>>(enc, W, out);
    softmax_kernel<<<BATCH, 256>>>(out);
}

// round 8
// speedup vs baseline: 1.0892x; 1.0892x over previous
#include <cuda_runtime.h>
#include <math.h>

#define DEC_DIM 1024
#define ENC_DIM 1024
#define BATCH   32
#define SRCLEN  2048

// ---------------------------------------------------------------------------
// Kernel 1: out[b*SRCLEN + s] = enc[s,b,:] . w_enc      (raw dot, no tanh yet)
// One warp per (s,b) row; r = s*32 + b matches enc memory order so
// consecutive warps stream consecutive 4KB rows. w_enc staged in shared.
// 268 MB read once -> HBM-bound, ~40us at ~6.7 TB/s.
// ---------------------------------------------------------------------------
__global__ void __launch_bounds__(256)
score_kernel(const float* __restrict__ enc,   // [SRCLEN][BATCH][ENC_DIM]
             const float* __restrict__ W,     // w_enc = W + DEC_DIM
             float* __restrict__ out) {
    __shared__ float4 s_w[ENC_DIM / 4];
    const float4* we = reinterpret_cast<const float4*>(W + DEC_DIM);
    for (int i = threadIdx.x; i < ENC_DIM / 4; i += blockDim.x) s_w[i] = we[i];
    __syncthreads();

    const int warp = threadIdx.x >> 5;
    const int lane = threadIdx.x & 31;
    const int r = blockIdx.x * 8 + warp;          // r = s*32 + b, < 65536
    const float4* row = reinterpret_cast<const float4*>(enc) + (long long)r * (ENC_DIM / 4);

    float sum = 0.f;
#pragma unroll
    for (int i = 0; i < 8; i++) {
        float4 a = __ldcs(row + lane + 32 * i);   // streaming: no reuse, 268MB > L2
        float4 w = s_w[lane + 32 * i];
        sum += a.x * w.x + a.y * w.y + a.z * w.z + a.w * w.w;
    }
#pragma unroll
    for (int o = 16; o; o >>= 1) sum += __shfl_xor_sync(0xffffffffu, sum, o);

    if (lane == 0) {
        const int b = r & 31;
        const int s = r >> 5;
        out[b * SRCLEN + s] = sum;
    }
}

// ---------------------------------------------------------------------------
// Kernel 2 (fused): per batch row b:
//   e_dec = dec_hidden[b,:] . W[0,:1024] + bias
//   v[s]  = tanh(out[b,s] + e_dec);  out[b,:] = softmax(v)
// 32 blocks x 256 threads. The e_dec dot costs 8KB of reads per block.
// ---------------------------------------------------------------------------
__global__ void __launch_bounds__(256)
softmax_kernel(const float* __restrict__ dec_hidden,
               const float* __restrict__ W,
               const float* __restrict__ bias,
               float* __restrict__ out) {
    const int b = blockIdx.x;
    const int t = threadIdx.x;
    const int lane = t & 31;
    const int warp = t >> 5;
    float* row = out + b * SRCLEN;

    __shared__ float red[8];
    __shared__ float s_bcast;

    // ---- e_dec: 256 threads x 1 float4 each over the 1024-dim dot ----
    {
        const float4* dh = reinterpret_cast<const float4*>(dec_hidden + b * DEC_DIM);
        const float4* wd = reinterpret_cast<const float4*>(W);
        float4 a = dh[t];
        float4 w = wd[t];
        float s = a.x * w.x + a.y * w.y + a.z * w.z + a.w * w.w;
#pragma unroll
        for (int o = 16; o; o >>= 1) s += __shfl_xor_sync(0xffffffffu, s, o);
        if (lane == 0) red[warp] = s;
        __syncthreads();
        if (t == 0) {
            float tot = red[0];
#pragma unroll
            for (int i = 1; i < 8; i++) tot += red[i];
            s_bcast = tot + bias[0];
        }
        __syncthreads();
    }
    const float edec = s_bcast;
    __syncthreads();  // protect s_bcast before reuse below

    // ---- load scores, tanh, softmax ----
    float v[8];
    float mx = -1e30f;
#pragma unroll
    for (int i = 0; i < 8; i++) {
        v[i] = tanhf(row[t + 256 * i] + edec);
        mx = fmaxf(mx, v[i]);
    }
#pragma unroll
    for (int o = 16; o; o >>= 1) mx = fmaxf(mx, __shfl_xor_sync(0xffffffffu, mx, o));
    if (lane == 0) red[warp] = mx;
    __syncthreads();
    if (t == 0) {
        float m = red[0];
#pragma unroll
        for (int i = 1; i < 8; i++) m = fmaxf(m, red[i]);
        s_bcast = m;
    }
    __syncthreads();
    const float m = s_bcast;
    __syncthreads();

    float s = 0.f;
#pragma unroll
    for (int i = 0; i < 8; i++) {
        v[i] = expf(v[i] - m);
        s += v[i];
    }
#pragma unroll
    for (int o = 16; o; o >>= 1) s += __shfl_xor_sync(0xffffffffu, s, o);
    if (lane == 0) red[warp] = s;
    __syncthreads();
    if (t == 0) {
        float tot = red[0];
#pragma unroll
        for (int i = 1; i < 8; i++) tot += red[i];
        s_bcast = 1.0f / tot;
    }
    __syncthreads();
    const float inv = s_bcast;

#pragma unroll
    for (int i = 0; i < 8; i++) row[t + 256 * i] = v[i] * inv;
}

// ---------------------------------------------------------------------------
extern "C" void kernel_launch(void* const* d_in, const int* in_sizes, int n_in,
                              void* d_out, int out_size) {
    const float* dec_hidden = (const float*)d_in[0];
    const float* enc        = (const float*)d_in[1];
    const float* W          = (const float*)d_in[2];
    const float* bias       = (const float*)d_in[3];
    float* out = (float*)d_out;

    score_kernel<<<(SRCLEN * BATCH) / 8, 256>>>(enc, W, out);
    softmax_kernel<<<BATCH, 256>>>(dec_hidden, W, bias, out);
}